// round 4
// baseline (speedup 1.0000x reference)
#include <cuda_runtime.h>
#include <cuda_bf16.h>
#include <cstdint>

#define N_NODES 100000
#define N_EDGES 1600000
#define NF 128
#define NEG_SLOPE 0.02f
#define EPSN 1e-5f

#if defined(__CUDA_ARCH_FEAT_SM103_ALL) ||                                        \
    (defined(__CUDA_ARCH_SPECIFIC__) && (__CUDA_ARCH_SPECIFIC__ == 1030)) ||      \
    (defined(__CUDA_ARCH_FAMILY_SPECIFIC__) && (__CUDA_ARCH_FAMILY_SPECIFIC__ == 1030))
#define HAS_TC 1
#else
#define HAS_TC 0
#endif

// ---------------- scratch (static device memory; no allocs) ----------------
__device__ uint2    g_hq[(size_t)N_NODES * 32];   // int16 h, 128 cols/row
__device__ uint2    g_mq[(size_t)N_NODES * 32];   // int16 m
__device__ unsigned g_wq[128 * 256];              // packed bf16 hi|lo of W'=W*qs
__device__ float4   g_raw[(size_t)N_NODES * 32];  // pre-norm fp32
__device__ int      g_deg[N_NODES];
__device__ int      g_rowptr[N_NODES + 1];
__device__ int      g_cursor[N_NODES];
__device__ int      g_col[N_EDGES];
__device__ float    g_stats[512];   // [0:128) sum, [128:256) sumsq, [256:384) umin, [384:512) umax
__device__ float    g_scale[NF];
__device__ float    g_shift[NF];
__device__ float    g_qs[NF];       // quant scale of current h
__device__ float    g_invq[NF];
__device__ unsigned g_absx[NF];

// ---------------- helpers ----------------
__device__ __forceinline__ uint32_t smem_u32(const void* p) {
    uint32_t a;
    asm("{ .reg .u64 t; cvta.to.shared.u64 t, %1; cvt.u32.u64 %0, t; }" : "=r"(a) : "l"(p));
    return a;
}
// packed bf16 pair: hi = bf16(v), lo = bf16(v - hi); word = hi<<16 | lo
__device__ __forceinline__ unsigned packf(float v) {
    unsigned hb = (unsigned)__bfloat16_as_ushort(__float2bfloat16(v));
    float hf = __uint_as_float(hb << 16);
    unsigned lb = (unsigned)__bfloat16_as_ushort(__float2bfloat16(v - hf));
    return (hb << 16) | lb;
}
__device__ __forceinline__ float unpackf(unsigned p) {
    return __uint_as_float(p & 0xFFFF0000u) + __uint_as_float(p << 16);
}
__device__ __forceinline__ unsigned f_ord(float f) {
    unsigned u = __float_as_uint(f);
    return (u & 0x80000000u) ? ~u : (u | 0x80000000u);
}
__device__ __forceinline__ float f_deord(unsigned o) {
    return __uint_as_float((o & 0x80000000u) ? (o ^ 0x80000000u) : ~o);
}
__device__ __forceinline__ float lkrelu(float v) { return v > 0.f ? v : NEG_SLOPE * v; }
__device__ __forceinline__ unsigned q2pack(float a, float b, float ia, float ib) {
    int q0 = __float2int_rn(a * ia);
    int q1 = __float2int_rn(b * ib);
    q0 = min(32767, max(-32767, q0));
    q1 = min(32767, max(-32767, q1));
    return (unsigned)(q0 & 0xFFFF) | ((unsigned)q1 << 16);
}

#if HAS_TC
__device__ __forceinline__ uint32_t elect_one() {
    uint32_t pred;
    asm volatile("{ .reg .pred p; elect.sync _|p, 0xFFFFFFFF; selp.b32 %0,1,0,p; }" : "=r"(pred));
    return pred;
}
#define MBAR_INIT(a, n) asm volatile("mbarrier.init.shared.b64 [%0], %1;" :: "r"(a), "r"(n) : "memory")
#define MBAR_WAIT(a, ph) do {                                                        \
    uint32_t _m = (a), _p = (ph), _d;                                                \
    asm volatile("{ .reg .pred p; mbarrier.try_wait.parity.acquire.cta.shared::cta.b64 p, [%1], %2;" \
                 " selp.b32 %0,1,0,p; }" : "=r"(_d) : "r"(_m), "r"(_p) : "memory");  \
    if (!_d) {                                                                       \
        asm volatile("{ .reg .pred P1; WL_%=:"                                       \
                     " mbarrier.try_wait.parity.acquire.cta.shared::cta.b64 P1, [%0], %1, 0x989680;" \
                     " @P1 bra.uni WD_%=; bra.uni WL_%=; WD_%=: }"                   \
                     :: "r"(_m), "r"(_p) : "memory");                                \
    } } while (0)
#define TC_ALLOC(sm, n)   asm volatile("tcgen05.alloc.cta_group::1.sync.aligned.shared::cta.b32 [%0], %1;" :: "r"(sm), "r"(n) : "memory")
#define TC_RELINQ()       asm volatile("tcgen05.relinquish_alloc_permit.cta_group::1.sync.aligned;")
#define TC_DEALLOC(t, n)  asm volatile("tcgen05.dealloc.cta_group::1.sync.aligned.b32 %0, %1;" :: "r"(t), "r"(n))
#define TC_COMMIT(mb)     asm volatile("tcgen05.commit.cta_group::1.mbarrier::arrive::one.shared::cluster.b64 [%0];" :: "r"(mb) : "memory")
#define TC_WAIT_LD()      asm volatile("tcgen05.wait::ld.sync.aligned;" ::: "memory")
#define TC_FENCE_AFTER()  asm volatile("tcgen05.fence::after_thread_sync;" ::: "memory")

#define TC_LD_X32(r, addr)                                                     \
    asm volatile("tcgen05.ld.sync.aligned.32x32b.x32.b32 "                     \
        "{%0,%1,%2,%3,%4,%5,%6,%7,%8,%9,%10,%11,%12,%13,%14,%15,"              \
        "%16,%17,%18,%19,%20,%21,%22,%23,%24,%25,%26,%27,%28,%29,%30,%31}, [%32];" \
        : "=r"((r)[0]),"=r"((r)[1]),"=r"((r)[2]),"=r"((r)[3]),                 \
          "=r"((r)[4]),"=r"((r)[5]),"=r"((r)[6]),"=r"((r)[7]),                 \
          "=r"((r)[8]),"=r"((r)[9]),"=r"((r)[10]),"=r"((r)[11]),               \
          "=r"((r)[12]),"=r"((r)[13]),"=r"((r)[14]),"=r"((r)[15]),             \
          "=r"((r)[16]),"=r"((r)[17]),"=r"((r)[18]),"=r"((r)[19]),             \
          "=r"((r)[20]),"=r"((r)[21]),"=r"((r)[22]),"=r"((r)[23]),             \
          "=r"((r)[24]),"=r"((r)[25]),"=r"((r)[26]),"=r"((r)[27]),             \
          "=r"((r)[28]),"=r"((r)[29]),"=r"((r)[30]),"=r"((r)[31])              \
        : "r"(addr))

static __device__ __forceinline__ uint64_t make_desc(uint32_t addr) {
    const uint64_t base = (uint64_t(2) << 61) | (uint64_t(1) << 46) |
                          (uint64_t(64) << 32) | (uint64_t(1) << 16);
    return base | ((uint64_t)(addr >> 4) & 0x3FFF);
}
__device__ __forceinline__ void mma_f16_ss(uint32_t d, uint64_t a, uint64_t b,
                                           uint32_t idesc, uint32_t en) {
    asm volatile(
        "{ .reg .pred p; setp.ne.u32 p, %5, 0;"
        " tcgen05.mma.cta_group::1.kind::f16 [%0], %1, %2, %3, {%4,%4,%4,%4}, p; }"
        :: "r"(d), "l"(a), "l"(b), "r"(idesc), "r"(0u), "r"(en) : "memory");
}
#endif  // HAS_TC

// ---------------- CSR build ----------------
__global__ void k_zero_deg(int* deg) {
    int i = blockIdx.x * 256 + threadIdx.x;
    if (i < N_NODES) deg[i] = 0;
}
__global__ void k_count(const int* __restrict__ dst, int* __restrict__ deg) {
    int i = blockIdx.x * 256 + threadIdx.x;
    if (i < N_EDGES) atomicAdd(&deg[dst[i]], 1);
}
__global__ void k_scan(const int* __restrict__ deg, int* __restrict__ rowptr,
                       int* __restrict__ cursor) {
    __shared__ int sh[1024];
    int t = threadIdx.x;
    const int C = (N_NODES + 1023) / 1024;
    int base = t * C;
    int s = 0;
    for (int i = 0; i < C; i++) {
        int idx = base + i;
        if (idx < N_NODES) s += deg[idx];
    }
    sh[t] = s;
    __syncthreads();
    for (int d = 1; d < 1024; d <<= 1) {
        int v = (t >= d) ? sh[t - d] : 0;
        __syncthreads();
        sh[t] += v;
        __syncthreads();
    }
    int run = sh[t] - s;
    for (int i = 0; i < C; i++) {
        int idx = base + i;
        if (idx < N_NODES) {
            rowptr[idx] = run;
            cursor[idx] = run;
            run += deg[idx];
        }
    }
    if (t == 1023) rowptr[N_NODES] = sh[1023];
}
__global__ void k_fill(const int* __restrict__ src, const int* __restrict__ dst,
                       int* __restrict__ cursor, int* __restrict__ col) {
    int i = blockIdx.x * 256 + threadIdx.x;
    if (i < N_EDGES) {
        int d = dst[i];
        int p = atomicAdd(&cursor[d], 1);
        col[p] = src[i];
    }
}

// ---------------- x quantization ----------------
__global__ void k_xzero(unsigned* absx) { absx[threadIdx.x] = 0u; }

__global__ void k_xabs(const float* __restrict__ x, unsigned* __restrict__ absx) {
    int c = threadIdx.x;
    float m = 0.f;
    for (int r = blockIdx.x; r < N_NODES; r += gridDim.x)
        m = fmaxf(m, fabsf(x[(size_t)r * 128 + c]));
    atomicMax(&absx[c], __float_as_uint(m));  // nonneg floats: bit order == value order
}
__global__ void k_xscale(const unsigned* __restrict__ absx, float* __restrict__ qs,
                         float* __restrict__ invq) {
    int c = threadIdx.x;
    float am = __uint_as_float(absx[c]);
    qs[c] = (am > 0.f) ? am / 32767.0f : 1.0f;
    invq[c] = (am > 0.f) ? 32767.0f / am : 0.0f;
}
__global__ void k_xq(const float2* __restrict__ x2, unsigned* __restrict__ hq,
                     const float* __restrict__ invq) {
    int i = blockIdx.x * 256 + threadIdx.x;
    if (i >= N_NODES * 64) return;
    int c2 = i & 63;
    float2 v = __ldg(&x2[i]);
    hq[i] = q2pack(v.x, v.y, invq[2 * c2], invq[2 * c2 + 1]);
}

// ---------------- W' prep: pack(W * qs) per layer ----------------
__global__ void k_wprep(const float* __restrict__ wl, const float* __restrict__ wr,
                        const float* __restrict__ qs, unsigned* __restrict__ wq) {
    int idx = blockIdx.x * 256 + threadIdx.x;  // 32768
    int o = idx >> 8, k = idx & 255;
    float v = ((k < 128) ? wl[o * 128 + k] : wr[o * 128 + (k - 128)]) * qs[k & 127];
    wq[idx] = packf(v);
}

// ---------------- segment-max gather: int16 SIMD max ----------------
__global__ void k_gather(const uint2* __restrict__ hq, const int* __restrict__ rowptr,
                         const int* __restrict__ col, uint2* __restrict__ mq) {
    int node = blockIdx.x * 8 + (threadIdx.x >> 5);
    if (node >= N_NODES) return;
    int lane = threadIdx.x & 31;
    int beg = __ldg(&rowptr[node]);
    int end = __ldg(&rowptr[node + 1]);
    unsigned a0 = 0x80008000u, a1 = 0x80008000u;
    int e = beg;
    for (; e + 3 < end; e += 4) {
        int s0 = __ldg(&col[e]), s1 = __ldg(&col[e + 1]);
        int s2 = __ldg(&col[e + 2]), s3 = __ldg(&col[e + 3]);
        uint2 p0 = __ldg(&hq[(size_t)s0 * 32 + lane]);
        uint2 p1 = __ldg(&hq[(size_t)s1 * 32 + lane]);
        uint2 p2 = __ldg(&hq[(size_t)s2 * 32 + lane]);
        uint2 p3 = __ldg(&hq[(size_t)s3 * 32 + lane]);
        a0 = __vmaxs2(a0, __vmaxs2(__vmaxs2(p0.x, p1.x), __vmaxs2(p2.x, p3.x)));
        a1 = __vmaxs2(a1, __vmaxs2(__vmaxs2(p0.y, p1.y), __vmaxs2(p2.y, p3.y)));
    }
    for (; e < end; e++) {
        int s = __ldg(&col[e]);
        uint2 p = __ldg(&hq[(size_t)s * 32 + lane]);
        a0 = __vmaxs2(a0, p.x);
        a1 = __vmaxs2(a1, p.y);
    }
    if (beg == end) { a0 = 0u; a1 = 0u; }
    uint2 o; o.x = a0; o.y = a1;
    mq[(size_t)node * 32 + lane] = o;
}

// ---------------- tcgen05 fused dual GEMM + bias + column stats/minmax -------
// D[128x128] per CTA = Aq[128x256] @ W'[128x256]^T, Aq=[mq|hq] int16 split
// exactly into bf16 hi/lo, W' split bf16 hi/lo, 4 MMA terms, fp32 TMEM accum.
#define GEMM_DYN (131072 + 1024)

#if HAS_TC
#define IDESC_BF16 ((1u << 4) | (1u << 7) | (1u << 10) | (16u << 17) | (8u << 24))

// A loader: int16 chunk (128 rows x 64 cols) -> exact bf16 hi/lo SW128 tiles
__device__ __forceinline__ void load_tile_a(uint32_t sm_hi, uint32_t sm_lo,
                                            const uint4* __restrict__ gp4,
                                            int row_base, int col_u, int tid) {
#pragma unroll
    for (int it = 0; it < 4; it++) {
        int unit = it * 256 + tid;   // 1024 units (128 rows x 8 x 16B)
        int row = unit >> 3;
        int u = unit & 7;
        uint4 p = make_uint4(0u, 0u, 0u, 0u);
        int gr = row_base + row;
        if (gr < N_NODES) p = __ldg(&gp4[(size_t)gr * 16 + col_u + u]);
        unsigned w[4] = {p.x, p.y, p.z, p.w};
        unsigned hw[4], lw[4];
#pragma unroll
        for (int j = 0; j < 4; j++) {
            int q0 = (int)(short)(w[j] & 0xFFFFu);
            int q1 = (int)(short)(w[j] >> 16);
            int l0 = ((q0 + 128) & 255) - 128;
            int l1 = ((q1 + 128) & 255) - 128;
            float fh0 = (float)(q0 - l0), fh1 = (float)(q1 - l1);
            float fl0 = (float)l0, fl1 = (float)l1;
            asm("cvt.rn.bf16x2.f32 %0, %1, %2;" : "=r"(hw[j]) : "f"(fh1), "f"(fh0));
            asm("cvt.rn.bf16x2.f32 %0, %1, %2;" : "=r"(lw[j]) : "f"(fl1), "f"(fl0));
        }
        uint32_t boff = row * 128 + u * 16;
        uint32_t sw = boff ^ ((boff >> 3) & 0x70);
        asm volatile("st.shared.v4.b32 [%0], {%1,%2,%3,%4};"
                     :: "r"(sm_hi + sw), "r"(hw[0]), "r"(hw[1]), "r"(hw[2]), "r"(hw[3]));
        asm volatile("st.shared.v4.b32 [%0], {%1,%2,%3,%4};"
                     :: "r"(sm_lo + sw), "r"(lw[0]), "r"(lw[1]), "r"(lw[2]), "r"(lw[3]));
    }
}

// W loader: packed-u32 chunk (128 rows x 64 cols) -> bf16 hi/lo SW128 tiles
__device__ __forceinline__ void load_tile_w(uint32_t sm_hi, uint32_t sm_lo,
                                            const uint4* __restrict__ gp4,
                                            int col_u, int tid) {
#pragma unroll
    for (int it = 0; it < 8; it++) {
        int unit = it * 256 + tid;   // 2048 units (128 rows x 16 x 8B)
        int row = unit >> 4;
        int u = unit & 15;
        uint4 p = __ldg(&gp4[(size_t)row * 64 + col_u + u]);
        unsigned hi0 = (p.x >> 16) | (p.y & 0xFFFF0000u);
        unsigned hi1 = (p.z >> 16) | (p.w & 0xFFFF0000u);
        unsigned lo0 = (p.x & 0xFFFFu) | (p.y << 16);
        unsigned lo1 = (p.z & 0xFFFFu) | (p.w << 16);
        uint32_t boff = row * 128 + u * 8;
        uint32_t sw = boff ^ ((boff >> 3) & 0x70);
        asm volatile("st.shared.v2.b32 [%0], {%1,%2};" :: "r"(sm_hi + sw), "r"(hi0), "r"(hi1));
        asm volatile("st.shared.v2.b32 [%0], {%1,%2};" :: "r"(sm_lo + sw), "r"(lo0), "r"(lo1));
    }
}
#endif

__global__ __launch_bounds__(256, 1)
void k_gemm(const uint4* __restrict__ Amq, const uint4* __restrict__ Ahq,
            const uint4* __restrict__ Wq, const float* __restrict__ bias,
            float4* __restrict__ out4, float* __restrict__ stats) {
    extern __shared__ char dyn[];
    int tid = threadIdx.x;
    int row0 = blockIdx.x * 128;
    float* stage = (float*)dyn;   // [128][132] fp32 staging (aliases load bufs)
    const uint32_t CTRL = 131072;
    float* sbias = (float*)(dyn + CTRL + 128);
    if (tid < 128) sbias[tid] = __ldg(&bias[tid]);

#if HAS_TC
    uint32_t sb = smem_u32(dyn);
    uint32_t mbar[2];
    mbar[0] = sb + CTRL;
    mbar[1] = sb + CTRL + 8;
    uint32_t tptr = sb + CTRL + 16;
    int wid = tid >> 5;
    int lane = tid & 31;

    if (wid == 0) { TC_ALLOC(tptr, 128); TC_RELINQ(); }
    if (tid == 0) { MBAR_INIT(mbar[0], 1); MBAR_INIT(mbar[1], 1); }
    __syncthreads();
    uint32_t tmem;
    asm volatile("ld.shared.b32 %0, [%1];" : "=r"(tmem) : "r"(tptr));

#pragma unroll 1
    for (int c = 0; c < 4; c++) {
        uint32_t so = sb + (c & 1) * 65536;
        if (c >= 2) { MBAR_WAIT(mbar[c & 1], 0); }
        const uint4* Ap = (c < 2) ? Amq : Ahq;
        load_tile_a(so, so + 16384, Ap, row0, (c & 1) * 8, tid);
        load_tile_w(so + 32768, so + 49152, Wq, c * 16, tid);
        asm volatile("fence.proxy.async.shared::cta;" ::: "memory");
        __syncthreads();
        if (wid == 0) {
            if (elect_one()) {
                uint64_t da_h = make_desc(so);
                uint64_t da_l = make_desc(so + 16384);
                uint64_t dw_h = make_desc(so + 32768);
                uint64_t dw_l = make_desc(so + 49152);
#pragma unroll
                for (int s = 0; s < 4; s++)
                    mma_f16_ss(tmem, da_h + s * 2, dw_h + s * 2, IDESC_BF16,
                               (c == 0 && s == 0) ? 0u : 1u);
#pragma unroll
                for (int s = 0; s < 4; s++)
                    mma_f16_ss(tmem, da_l + s * 2, dw_h + s * 2, IDESC_BF16, 1u);
#pragma unroll
                for (int s = 0; s < 4; s++)
                    mma_f16_ss(tmem, da_h + s * 2, dw_l + s * 2, IDESC_BF16, 1u);
#pragma unroll
                for (int s = 0; s < 4; s++)
                    mma_f16_ss(tmem, da_l + s * 2, dw_l + s * 2, IDESC_BF16, 1u);
                TC_COMMIT(mbar[c & 1]);
            }
        }
    }
    MBAR_WAIT(mbar[1], 1);
    TC_FENCE_AFTER();

    if (wid < 4) {
        uint32_t dr[128];
        TC_LD_X32(dr, tmem);
        TC_LD_X32(dr + 32, tmem + 32);
        TC_LD_X32(dr + 64, tmem + 64);
        TC_LD_X32(dr + 96, tmem + 96);
        TC_WAIT_LD();
        int r = wid * 32 + lane;
        bool valid = (row0 + r) < N_NODES;
#pragma unroll
        for (int cc = 0; cc < 128; cc++)
            stage[r * 132 + cc] = valid ? (__uint_as_float(dr[cc]) + sbias[cc]) : 0.0f;
    }
    __syncthreads();
#else
    // Fallback (compute_103 PTX target only; never runs on GB300 — the fatbin's
    // sm_103a cubin wins at load time).
    __syncthreads();
    {
        int r = tid >> 1;
        int c0 = (tid & 1) * 64;
        int gr = row0 + r;
        const short* Am = (const short*)Amq;
        const short* Ah = (const short*)Ahq;
        const unsigned* W = (const unsigned*)Wq;
        for (int j = 0; j < 64; j++) {
            float acc = 0.f;
            if (gr < N_NODES) {
                for (int k = 0; k < 256; k++) {
                    float av = (float)((k < 128) ? Am[(size_t)gr * 128 + k]
                                                 : Ah[(size_t)gr * 128 + (k - 128)]);
                    acc += av * unpackf(W[(size_t)(c0 + j) * 256 + k]);
                }
            }
            stage[r * 132 + c0 + j] = (gr < N_NODES) ? (acc + sbias[c0 + j]) : 0.0f;
        }
    }
    __syncthreads();
#endif

    // epilogue: column sum/sumsq + min/max + coalesced store
    if (tid < 128) {
        float s = 0.f, s2 = 0.f;
        float mn = __int_as_float(0x7f800000), mx = -mn;
#pragma unroll 8
        for (int r = 0; r < 128; r++) {
            float v = stage[r * 132 + tid];
            s += v;
            s2 += v * v;
            mn = fminf(mn, v);
            mx = fmaxf(mx, v);
        }
        atomicAdd(&stats[tid], s);
        atomicAdd(&stats[128 + tid], s2);
        atomicMin((unsigned*)stats + 256 + tid, f_ord(mn));
        atomicMax((unsigned*)stats + 384 + tid, f_ord(mx));
    }
#pragma unroll
    for (int it = 0; it < 16; it++) {
        int idx = it * 256 + tid;
        int row = idx >> 5, c4 = idx & 31;
        int gr = row0 + row;
        if (gr < N_NODES) {
            float4 o;
            o.x = stage[row * 132 + c4 * 4 + 0];
            o.y = stage[row * 132 + c4 * 4 + 1];
            o.z = stage[row * 132 + c4 * 4 + 2];
            o.w = stage[row * 132 + c4 * 4 + 3];
            out4[(size_t)gr * 32 + c4] = o;
        }
    }
#if HAS_TC
    __syncthreads();
    if ((tid >> 5) == 0) TC_DEALLOC(tmem, 128);
#endif
}

// ---------------- GraphNorm stats + quant scale ----------------
__global__ void k_zero_stats(float* st) {
    int t = threadIdx.x;
    if (t < 256) st[t] = 0.f;
    else if (t < 384) ((unsigned*)st)[t] = 0xFFFFFFFFu;  // umin init
    else ((unsigned*)st)[t] = 0u;                        // umax init
}

__global__ void k_stats(const float* __restrict__ st, const float* __restrict__ gamma,
                        const float* __restrict__ beta, const float* __restrict__ alpha,
                        float* __restrict__ scale, float* __restrict__ shift,
                        float* __restrict__ qs, float* __restrict__ invq) {
    int c = threadIdx.x;
    const float invN = 1.0f / (float)N_NODES;
    float mu = st[c] * invN;
    float a = alpha[c];
    float var = st[c + 128] * invN + mu * mu * (a * a - 2.f * a);
    float r = rsqrtf(var + EPSN);
    float g = gamma[c];
    float s = g * r;
    float t = beta[c] - g * a * mu * r;
    scale[c] = s;
    shift[c] = t;
    float rmin = f_deord(((const unsigned*)st)[256 + c]);
    float rmax = f_deord(((const unsigned*)st)[384 + c]);
    float e1 = lkrelu(s * rmin + t);
    float e2 = lkrelu(s * rmax + t);
    float am = fmaxf(fabsf(e1), fabsf(e2));
    qs[c] = (am > 0.f) ? am / 32767.0f : 1.0f;
    invq[c] = (am > 0.f) ? 32767.0f / am : 0.0f;
}

// ---------------- normalize + LeakyReLU + int16 quantize ----------------
__global__ void k_norm(const float4* __restrict__ raw, const float4* __restrict__ sc4,
                       const float4* __restrict__ sh4, const float4* __restrict__ iv4,
                       uint2* __restrict__ hq) {
    int i = blockIdx.x * 256 + threadIdx.x;
    if (i >= N_NODES * 32) return;
    int c4 = i & 31;
    float4 s = __ldg(&sc4[c4]);
    float4 t = __ldg(&sh4[c4]);
    float4 iv = __ldg(&iv4[c4]);
    float4 v = raw[i];
    float h0 = lkrelu(s.x * v.x + t.x);
    float h1 = lkrelu(s.y * v.y + t.y);
    float h2 = lkrelu(s.z * v.z + t.z);
    float h3 = lkrelu(s.w * v.w + t.w);
    uint2 o;
    o.x = q2pack(h0, h1, iv.x, iv.y);
    o.y = q2pack(h2, h3, iv.z, iv.w);
    hq[i] = o;
}

// ---------------- final SAGEConv (NF->3) + tanh*0.5 ----------------
__global__ void k_final(const uint2* __restrict__ mq, const uint2* __restrict__ hq,
                        const float* __restrict__ Wlo, const float* __restrict__ Wro,
                        const float* __restrict__ blo, const float4* __restrict__ qs4,
                        float* __restrict__ out) {
    __shared__ float4 swl[3][32];
    __shared__ float4 swr[3][32];
    __shared__ float sb[3];
    int tid = threadIdx.x;
    if (tid < 96) {
        int o = tid >> 5, l = tid & 31;
        swl[o][l] = ((const float4*)Wlo)[o * 32 + l];
        swr[o][l] = ((const float4*)Wro)[o * 32 + l];
    }
    if (tid < 3) sb[tid] = blo[tid];
    __syncthreads();

    int node = blockIdx.x * 8 + (tid >> 5);
    if (node >= N_NODES) return;
    int lane = tid & 31;
    float4 qs = __ldg(&qs4[lane]);
    uint2 mv2 = mq[(size_t)node * 32 + lane];
    uint2 hv2 = hq[(size_t)node * 32 + lane];
    float mv[4] = {(float)(short)(mv2.x & 0xFFFF) * qs.x, (float)(short)(mv2.x >> 16) * qs.y,
                   (float)(short)(mv2.y & 0xFFFF) * qs.z, (float)(short)(mv2.y >> 16) * qs.w};
    float hv[4] = {(float)(short)(hv2.x & 0xFFFF) * qs.x, (float)(short)(hv2.x >> 16) * qs.y,
                   (float)(short)(hv2.y & 0xFFFF) * qs.z, (float)(short)(hv2.y >> 16) * qs.w};
    float p[3];
#pragma unroll
    for (int o = 0; o < 3; o++) {
        float4 wl = swl[o][lane];
        float4 wr = swr[o][lane];
        p[o] = mv[0] * wl.x + mv[1] * wl.y + mv[2] * wl.z + mv[3] * wl.w +
               hv[0] * wr.x + hv[1] * wr.y + hv[2] * wr.z + hv[3] * wr.w;
    }
#pragma unroll
    for (int d = 16; d; d >>= 1) {
#pragma unroll
        for (int o = 0; o < 3; o++) p[o] += __shfl_down_sync(0xffffffffu, p[o], d);
    }
    if (lane == 0) {
#pragma unroll
        for (int o = 0; o < 3; o++)
            out[(size_t)node * 3 + o] = tanhf(p[o] + sb[o]) * 0.5f;
    }
}

// ---------------- host launcher ----------------
extern "C" void kernel_launch(void* const* d_in, const int* in_sizes, int n_in,
                              void* d_out, int out_size) {
    const float* x     = (const float*)d_in[0];
    const int*   ei    = (const int*)d_in[1];
    const float* Wl    = (const float*)d_in[2];
    const float* bl    = (const float*)d_in[3];
    const float* Wr    = (const float*)d_in[4];
    const float* Wlo   = (const float*)d_in[5];
    const float* blo   = (const float*)d_in[6];
    const float* Wro   = (const float*)d_in[7];
    const float* gamma = (const float*)d_in[8];
    const float* beta  = (const float*)d_in[9];
    const float* alpha = (const float*)d_in[10];

    uint2 *hq, *mq;
    unsigned *wq, *absx;
    float4* raw;
    float *stats, *scale, *shift, *qs, *invq;
    int *deg, *rowptr, *cursor, *col;
    cudaGetSymbolAddress((void**)&hq, g_hq);
    cudaGetSymbolAddress((void**)&mq, g_mq);
    cudaGetSymbolAddress((void**)&wq, g_wq);
    cudaGetSymbolAddress((void**)&absx, g_absx);
    cudaGetSymbolAddress((void**)&raw, g_raw);
    cudaGetSymbolAddress((void**)&stats, g_stats);
    cudaGetSymbolAddress((void**)&scale, g_scale);
    cudaGetSymbolAddress((void**)&shift, g_shift);
    cudaGetSymbolAddress((void**)&qs, g_qs);
    cudaGetSymbolAddress((void**)&invq, g_invq);
    cudaGetSymbolAddress((void**)&deg, g_deg);
    cudaGetSymbolAddress((void**)&rowptr, g_rowptr);
    cudaGetSymbolAddress((void**)&cursor, g_cursor);
    cudaGetSymbolAddress((void**)&col, g_col);

    cudaFuncSetAttribute(k_gemm, cudaFuncAttributeMaxDynamicSharedMemorySize, GEMM_DYN);

    const int* src = ei;
    const int* dst = ei + N_EDGES;

    // CSR build
    k_zero_deg<<<(N_NODES + 255) / 256, 256>>>(deg);
    k_count<<<(N_EDGES + 255) / 256, 256>>>(dst, deg);
    k_scan<<<1, 1024>>>(deg, rowptr, cursor);
    k_fill<<<(N_EDGES + 255) / 256, 256>>>(src, dst, cursor, col);

    // x quantization
    k_xzero<<<1, 128>>>(absx);
    k_xabs<<<200, 128>>>(x, absx);
    k_xscale<<<1, 128>>>(absx, qs, invq);
    k_xq<<<(N_NODES * 64 + 255) / 256, 256>>>((const float2*)x, (unsigned*)hq, invq);

    const int gemm_grid = (N_NODES + 127) / 128;
    for (int L = 0; L < 6; L++) {
        k_gather<<<(N_NODES + 7) / 8, 256>>>(hq, rowptr, col, mq);
        k_zero_stats<<<1, 512>>>(stats);
        k_wprep<<<128, 256>>>(Wl + L * 16384, Wr + L * 16384, qs, wq);
        k_gemm<<<gemm_grid, 256, GEMM_DYN>>>((const uint4*)mq, (const uint4*)hq,
                                             (const uint4*)wq, bl + L * NF, raw, stats);
        k_stats<<<1, 128>>>(stats, gamma + L * NF, beta + L * NF, alpha + L * NF,
                            scale, shift, qs, invq);
        k_norm<<<(N_NODES * 32 + 255) / 256, 256>>>(raw, (const float4*)scale,
                                                    (const float4*)shift,
                                                    (const float4*)invq, hq);
    }
    k_gather<<<(N_NODES + 7) / 8, 256>>>(hq, rowptr, col, mq);
    k_final<<<(N_NODES + 7) / 8, 256>>>(mq, hq, Wlo, Wro, blo, (const float4*)qs,
                                        (float*)d_out);
}

// round 5
// speedup vs baseline: 1.1185x; 1.1185x over previous
#include <cuda_runtime.h>
#include <cuda_bf16.h>
#include <cstdint>

#define N_NODES 100000
#define N_EDGES 1600000
#define NF 128
#define NEG_SLOPE 0.02f
#define EPSN 1e-5f

#if defined(__CUDA_ARCH_FEAT_SM103_ALL) ||                                        \
    (defined(__CUDA_ARCH_SPECIFIC__) && (__CUDA_ARCH_SPECIFIC__ == 1030)) ||      \
    (defined(__CUDA_ARCH_FAMILY_SPECIFIC__) && (__CUDA_ARCH_FAMILY_SPECIFIC__ == 1030))
#define HAS_TC 1
#else
#define HAS_TC 0
#endif

// ---------------- scratch (static device memory; no allocs) ----------------
__device__ float4   g_raw[(size_t)N_NODES * 32];  // pre-norm layer output (fp32)
__device__ uint4    g_mp[(size_t)N_NODES * 32];   // packed normalized m (hi|lo u32/col)
__device__ unsigned g_wp[6 * 128 * 256];          // packed [Wl|Wr] per layer
__device__ int      g_deg[N_NODES];
__device__ int      g_rowptr[N_NODES + 1];
__device__ int      g_cursor[N_NODES];
__device__ int      g_col[N_EDGES];
__device__ float    g_stats[2 * NF];
__device__ float    g_scale[NF];
__device__ float    g_shift[NF];

// ---------------- helpers ----------------
__device__ __forceinline__ uint32_t smem_u32(const void* p) {
    uint32_t a;
    asm("{ .reg .u64 t; cvta.to.shared.u64 t, %1; cvt.u32.u64 %0, t; }" : "=r"(a) : "l"(p));
    return a;
}
__device__ __forceinline__ float lkrelu(float v) { return v > 0.f ? v : NEG_SLOPE * v; }
// packed bf16 pair: hi = bf16(v), lo = bf16(v - hi); word = hi<<16 | lo
__device__ __forceinline__ unsigned packf(float v) {
    unsigned hb = (unsigned)__bfloat16_as_ushort(__float2bfloat16(v));
    float hf = __uint_as_float(hb << 16);
    unsigned lb = (unsigned)__bfloat16_as_ushort(__float2bfloat16(v - hf));
    return (hb << 16) | lb;
}
__device__ __forceinline__ float unpackf(unsigned p) {
    return __uint_as_float(p & 0xFFFF0000u) + __uint_as_float(p << 16);
}

#if HAS_TC
__device__ __forceinline__ uint32_t elect_one() {
    uint32_t pred;
    asm volatile("{ .reg .pred p; elect.sync _|p, 0xFFFFFFFF; selp.b32 %0,1,0,p; }" : "=r"(pred));
    return pred;
}
#define MBAR_INIT(a, n) asm volatile("mbarrier.init.shared.b64 [%0], %1;" :: "r"(a), "r"(n) : "memory")
#define MBAR_WAIT(a, ph) do {                                                        \
    uint32_t _m = (a), _p = (ph), _d;                                                \
    asm volatile("{ .reg .pred p; mbarrier.try_wait.parity.acquire.cta.shared::cta.b64 p, [%1], %2;" \
                 " selp.b32 %0,1,0,p; }" : "=r"(_d) : "r"(_m), "r"(_p) : "memory");  \
    if (!_d) {                                                                       \
        asm volatile("{ .reg .pred P1; WL_%=:"                                       \
                     " mbarrier.try_wait.parity.acquire.cta.shared::cta.b64 P1, [%0], %1, 0x989680;" \
                     " @P1 bra.uni WD_%=; bra.uni WL_%=; WD_%=: }"                   \
                     :: "r"(_m), "r"(_p) : "memory");                                \
    } } while (0)
#define TC_ALLOC(sm, n)   asm volatile("tcgen05.alloc.cta_group::1.sync.aligned.shared::cta.b32 [%0], %1;" :: "r"(sm), "r"(n) : "memory")
#define TC_RELINQ()       asm volatile("tcgen05.relinquish_alloc_permit.cta_group::1.sync.aligned;")
#define TC_DEALLOC(t, n)  asm volatile("tcgen05.dealloc.cta_group::1.sync.aligned.b32 %0, %1;" :: "r"(t), "r"(n))
#define TC_COMMIT(mb)     asm volatile("tcgen05.commit.cta_group::1.mbarrier::arrive::one.shared::cluster.b64 [%0];" :: "r"(mb) : "memory")
#define TC_WAIT_LD()      asm volatile("tcgen05.wait::ld.sync.aligned;" ::: "memory")
#define TC_FENCE_AFTER()  asm volatile("tcgen05.fence::after_thread_sync;" ::: "memory")

#define TC_LD_X32(r, addr)                                                     \
    asm volatile("tcgen05.ld.sync.aligned.32x32b.x32.b32 "                     \
        "{%0,%1,%2,%3,%4,%5,%6,%7,%8,%9,%10,%11,%12,%13,%14,%15,"              \
        "%16,%17,%18,%19,%20,%21,%22,%23,%24,%25,%26,%27,%28,%29,%30,%31}, [%32];" \
        : "=r"((r)[0]),"=r"((r)[1]),"=r"((r)[2]),"=r"((r)[3]),                 \
          "=r"((r)[4]),"=r"((r)[5]),"=r"((r)[6]),"=r"((r)[7]),                 \
          "=r"((r)[8]),"=r"((r)[9]),"=r"((r)[10]),"=r"((r)[11]),               \
          "=r"((r)[12]),"=r"((r)[13]),"=r"((r)[14]),"=r"((r)[15]),             \
          "=r"((r)[16]),"=r"((r)[17]),"=r"((r)[18]),"=r"((r)[19]),             \
          "=r"((r)[20]),"=r"((r)[21]),"=r"((r)[22]),"=r"((r)[23]),             \
          "=r"((r)[24]),"=r"((r)[25]),"=r"((r)[26]),"=r"((r)[27]),             \
          "=r"((r)[28]),"=r"((r)[29]),"=r"((r)[30]),"=r"((r)[31])              \
        : "r"(addr))

static __device__ __forceinline__ uint64_t make_desc(uint32_t addr) {
    const uint64_t base = (uint64_t(2) << 61) | (uint64_t(1) << 46) |
                          (uint64_t(64) << 32) | (uint64_t(1) << 16);
    return base | ((uint64_t)(addr >> 4) & 0x3FFF);
}
__device__ __forceinline__ void mma_f16_ss(uint32_t d, uint64_t a, uint64_t b,
                                           uint32_t idesc, uint32_t en) {
    asm volatile(
        "{ .reg .pred p; setp.ne.u32 p, %5, 0;"
        " tcgen05.mma.cta_group::1.kind::f16 [%0], %1, %2, %3, {%4,%4,%4,%4}, p; }"
        :: "r"(d), "l"(a), "l"(b), "r"(idesc), "r"(0u), "r"(en) : "memory");
}
#endif  // HAS_TC

// ---------------- CSR build ----------------
__global__ void k_zero_deg(int* deg) {
    int i = blockIdx.x * 256 + threadIdx.x;
    if (i < N_NODES) deg[i] = 0;
}
__global__ void k_count(const int* __restrict__ dst, int* __restrict__ deg) {
    int i = blockIdx.x * 256 + threadIdx.x;
    if (i < N_EDGES) atomicAdd(&deg[dst[i]], 1);
}
__global__ void k_scan(const int* __restrict__ deg, int* __restrict__ rowptr,
                       int* __restrict__ cursor) {
    __shared__ int sh[1024];
    int t = threadIdx.x;
    const int C = (N_NODES + 1023) / 1024;
    int base = t * C;
    int s = 0;
    for (int i = 0; i < C; i++) {
        int idx = base + i;
        if (idx < N_NODES) s += deg[idx];
    }
    sh[t] = s;
    __syncthreads();
    for (int d = 1; d < 1024; d <<= 1) {
        int v = (t >= d) ? sh[t - d] : 0;
        __syncthreads();
        sh[t] += v;
        __syncthreads();
    }
    int run = sh[t] - s;
    for (int i = 0; i < C; i++) {
        int idx = base + i;
        if (idx < N_NODES) {
            rowptr[idx] = run;
            cursor[idx] = run;
            run += deg[idx];
        }
    }
    if (t == 1023) rowptr[N_NODES] = sh[1023];
}
__global__ void k_fill(const int* __restrict__ src, const int* __restrict__ dst,
                       int* __restrict__ cursor, int* __restrict__ col) {
    int i = blockIdx.x * 256 + threadIdx.x;
    if (i < N_EDGES) {
        int d = dst[i];
        int p = atomicAdd(&cursor[d], 1);
        col[p] = src[i];
    }
}

// ---------------- weight pack (all 6 layers, once) ----------------
__global__ void k_wconv(const float* __restrict__ Wl, const float* __restrict__ Wr,
                        unsigned* __restrict__ wp) {
    int i = blockIdx.x * 256 + threadIdx.x;
    if (i >= 6 * 128 * 256) return;
    int L = i >> 15;
    int rem = i & 32767;
    int o = rem >> 8;
    int k = rem & 255;
    float v = (k < 128) ? Wl[L * 16384 + o * 128 + k] : Wr[L * 16384 + o * 128 + (k - 128)];
    wp[i] = packf(v);
}

// ---------------- gather: segment max/min over RAW, then norm + pack -------
// m_c = f_c(max raw_c) if scale_c>=0 else f_c(min raw_c); f = leaky(s*v+t).
// do_act==0 (layer 0): m_c = max raw_c (identity transform).
__global__ void k_gather(const float4* __restrict__ raw, const int* __restrict__ rowptr,
                         const int* __restrict__ col, uint4* __restrict__ mp,
                         const float4* __restrict__ sc4, const float4* __restrict__ sh4,
                         int do_act) {
    int node = blockIdx.x * 8 + (threadIdx.x >> 5);
    if (node >= N_NODES) return;
    int lane = threadIdx.x & 31;
    int beg = __ldg(&rowptr[node]);
    int end = __ldg(&rowptr[node + 1]);
    const float NINF = __int_as_float(0xff800000);
    const float PINF = __int_as_float(0x7f800000);
    float4 mx = make_float4(NINF, NINF, NINF, NINF);
    float4 mn = make_float4(PINF, PINF, PINF, PINF);
    int e = beg;
    for (; e + 3 < end; e += 4) {
        int s0 = __ldg(&col[e]), s1 = __ldg(&col[e + 1]);
        int s2 = __ldg(&col[e + 2]), s3 = __ldg(&col[e + 3]);
        float4 p0 = __ldg(&raw[(size_t)s0 * 32 + lane]);
        float4 p1 = __ldg(&raw[(size_t)s1 * 32 + lane]);
        float4 p2 = __ldg(&raw[(size_t)s2 * 32 + lane]);
        float4 p3 = __ldg(&raw[(size_t)s3 * 32 + lane]);
        mx.x = fmaxf(fmaxf(fmaxf(mx.x, p0.x), fmaxf(p1.x, p2.x)), p3.x);
        mx.y = fmaxf(fmaxf(fmaxf(mx.y, p0.y), fmaxf(p1.y, p2.y)), p3.y);
        mx.z = fmaxf(fmaxf(fmaxf(mx.z, p0.z), fmaxf(p1.z, p2.z)), p3.z);
        mx.w = fmaxf(fmaxf(fmaxf(mx.w, p0.w), fmaxf(p1.w, p2.w)), p3.w);
        mn.x = fminf(fminf(fminf(mn.x, p0.x), fminf(p1.x, p2.x)), p3.x);
        mn.y = fminf(fminf(fminf(mn.y, p0.y), fminf(p1.y, p2.y)), p3.y);
        mn.z = fminf(fminf(fminf(mn.z, p0.z), fminf(p1.z, p2.z)), p3.z);
        mn.w = fminf(fminf(fminf(mn.w, p0.w), fminf(p1.w, p2.w)), p3.w);
    }
    for (; e < end; e++) {
        int s = __ldg(&col[e]);
        float4 p = __ldg(&raw[(size_t)s * 32 + lane]);
        mx.x = fmaxf(mx.x, p.x); mx.y = fmaxf(mx.y, p.y);
        mx.z = fmaxf(mx.z, p.z); mx.w = fmaxf(mx.w, p.w);
        mn.x = fminf(mn.x, p.x); mn.y = fminf(mn.y, p.y);
        mn.z = fminf(mn.z, p.z); mn.w = fminf(mn.w, p.w);
    }
    uint4 o;
    if (beg == end) {
        o = make_uint4(0u, 0u, 0u, 0u);
    } else if (do_act) {
        float4 s = __ldg(&sc4[lane]);
        float4 t = __ldg(&sh4[lane]);
        float v0 = lkrelu(fmaf(s.x, (s.x >= 0.f) ? mx.x : mn.x, t.x));
        float v1 = lkrelu(fmaf(s.y, (s.y >= 0.f) ? mx.y : mn.y, t.y));
        float v2 = lkrelu(fmaf(s.z, (s.z >= 0.f) ? mx.z : mn.z, t.z));
        float v3 = lkrelu(fmaf(s.w, (s.w >= 0.f) ? mx.w : mn.w, t.w));
        o = make_uint4(packf(v0), packf(v1), packf(v2), packf(v3));
    } else {
        o = make_uint4(packf(mx.x), packf(mx.y), packf(mx.z), packf(mx.w));
    }
    mp[(size_t)node * 32 + lane] = o;
}

// ---------------- tcgen05 fused dual GEMM + bias + column stats -------------
#define GEMM_DYN (131072 + 1024)

#if HAS_TC
#define IDESC_BF16 ((1u << 4) | (1u << 7) | (1u << 10) | (16u << 17) | (8u << 24))

// packed-u32 loader (m tiles, W tiles) -> bf16 hi/lo SW128 tiles
__device__ __forceinline__ void load_tile_pk(uint32_t sm_hi, uint32_t sm_lo,
                                             const uint4* __restrict__ gp4, int row_base,
                                             int row_limit, int ld_u, int col_u, int tid) {
#pragma unroll
    for (int it = 0; it < 8; it++) {
        int unit = it * 256 + tid;   // 2048 units (128 rows x 16 x 16B)
        int row = unit >> 4;
        int u = unit & 15;
        uint4 p = make_uint4(0u, 0u, 0u, 0u);
        int gr = row_base + row;
        if (gr < row_limit) p = __ldg(&gp4[(size_t)gr * ld_u + col_u + u]);
        unsigned hi0 = (p.x >> 16) | (p.y & 0xFFFF0000u);
        unsigned hi1 = (p.z >> 16) | (p.w & 0xFFFF0000u);
        unsigned lo0 = (p.x & 0xFFFFu) | (p.y << 16);
        unsigned lo1 = (p.z & 0xFFFFu) | (p.w << 16);
        uint32_t boff = row * 128 + u * 8;
        uint32_t sw = boff ^ ((boff >> 3) & 0x70);
        asm volatile("st.shared.v2.b32 [%0], {%1,%2};" :: "r"(sm_hi + sw), "r"(hi0), "r"(hi1));
        asm volatile("st.shared.v2.b32 [%0], {%1,%2};" :: "r"(sm_lo + sw), "r"(lo0), "r"(lo1));
    }
}

// raw-fp32 loader with on-the-fly GraphNorm+LeakyReLU, then bf16 hi/lo split
__device__ __forceinline__ void load_tile_raw(uint32_t sm_hi, uint32_t sm_lo,
                                              const float4* __restrict__ raw, int row_base,
                                              int col_u, int tid,
                                              const float4* __restrict__ sc4,
                                              const float4* __restrict__ sh4, int do_act) {
#pragma unroll
    for (int it = 0; it < 8; it++) {
        int unit = it * 256 + tid;   // 2048 units (128 rows x 16 float4)
        int row = unit >> 4;
        int u = unit & 15;
        float4 v = make_float4(0.f, 0.f, 0.f, 0.f);
        int gr = row_base + row;
        if (gr < N_NODES) v = __ldg(&raw[(size_t)gr * 32 + col_u + u]);
        if (do_act) {
            float4 s = __ldg(&sc4[col_u + u]);
            float4 t = __ldg(&sh4[col_u + u]);
            v.x = lkrelu(fmaf(s.x, v.x, t.x));
            v.y = lkrelu(fmaf(s.y, v.y, t.y));
            v.z = lkrelu(fmaf(s.z, v.z, t.z));
            v.w = lkrelu(fmaf(s.w, v.w, t.w));
        }
        unsigned p0 = packf(v.x), p1 = packf(v.y), p2 = packf(v.z), p3 = packf(v.w);
        unsigned hi0 = (p0 >> 16) | (p1 & 0xFFFF0000u);
        unsigned hi1 = (p2 >> 16) | (p3 & 0xFFFF0000u);
        unsigned lo0 = (p0 & 0xFFFFu) | (p1 << 16);
        unsigned lo1 = (p2 & 0xFFFFu) | (p3 << 16);
        uint32_t boff = row * 128 + u * 8;
        uint32_t sw = boff ^ ((boff >> 3) & 0x70);
        asm volatile("st.shared.v2.b32 [%0], {%1,%2};" :: "r"(sm_hi + sw), "r"(hi0), "r"(hi1));
        asm volatile("st.shared.v2.b32 [%0], {%1,%2};" :: "r"(sm_lo + sw), "r"(lo0), "r"(lo1));
    }
}
#endif

__global__ __launch_bounds__(256, 1)
void k_gemm(const uint4* __restrict__ mp, const float4* __restrict__ rawin,
            const uint4* __restrict__ Wq, const float4* __restrict__ sc4,
            const float4* __restrict__ sh4, int do_act,
            const float* __restrict__ bias,
            float4* __restrict__ out4, float* __restrict__ stats) {
    extern __shared__ char dyn[];
    int tid = threadIdx.x;
    int row0 = blockIdx.x * 128;
    float* stage = (float*)dyn;   // [128][132] fp32 staging (aliases load bufs)
    const uint32_t CTRL = 131072;
    float* sbias = (float*)(dyn + CTRL + 128);
    if (tid < 128) sbias[tid] = __ldg(&bias[tid]);

#if HAS_TC
    uint32_t sb = smem_u32(dyn);
    uint32_t mbar[2];
    mbar[0] = sb + CTRL;
    mbar[1] = sb + CTRL + 8;
    uint32_t tptr = sb + CTRL + 16;
    int wid = tid >> 5;
    int lane = tid & 31;

    if (wid == 0) { TC_ALLOC(tptr, 128); TC_RELINQ(); }
    if (tid == 0) { MBAR_INIT(mbar[0], 1); MBAR_INIT(mbar[1], 1); }
    __syncthreads();
    uint32_t tmem;
    asm volatile("ld.shared.b32 %0, [%1];" : "=r"(tmem) : "r"(tptr));

#pragma unroll 1
    for (int c = 0; c < 4; c++) {
        uint32_t so = sb + (c & 1) * 65536;
        if (c >= 2) { MBAR_WAIT(mbar[c & 1], 0); }
        if (c < 2)
            load_tile_pk(so, so + 16384, mp, row0, N_NODES, 32, (c & 1) * 16, tid);
        else
            load_tile_raw(so, so + 16384, rawin, row0, (c & 1) * 16, tid, sc4, sh4, do_act);
        load_tile_pk(so + 32768, so + 49152, Wq, 0, 128, 64, c * 16, tid);
        asm volatile("fence.proxy.async.shared::cta;" ::: "memory");
        __syncthreads();
        if (wid == 0) {
            if (elect_one()) {
                uint64_t da_h = make_desc(so);
                uint64_t da_l = make_desc(so + 16384);
                uint64_t dw_h = make_desc(so + 32768);
                uint64_t dw_l = make_desc(so + 49152);
#pragma unroll
                for (int s = 0; s < 4; s++)
                    mma_f16_ss(tmem, da_h + s * 2, dw_h + s * 2, IDESC_BF16,
                               (c == 0 && s == 0) ? 0u : 1u);
#pragma unroll
                for (int s = 0; s < 4; s++)
                    mma_f16_ss(tmem, da_l + s * 2, dw_h + s * 2, IDESC_BF16, 1u);
#pragma unroll
                for (int s = 0; s < 4; s++)
                    mma_f16_ss(tmem, da_h + s * 2, dw_l + s * 2, IDESC_BF16, 1u);
                TC_COMMIT(mbar[c & 1]);
            }
        }
    }
    MBAR_WAIT(mbar[1], 1);
    TC_FENCE_AFTER();

    if (wid < 4) {
        uint32_t dr[128];
        TC_LD_X32(dr, tmem);
        TC_LD_X32(dr + 32, tmem + 32);
        TC_LD_X32(dr + 64, tmem + 64);
        TC_LD_X32(dr + 96, tmem + 96);
        TC_WAIT_LD();
        int r = wid * 32 + lane;
        bool valid = (row0 + r) < N_NODES;
#pragma unroll
        for (int cc = 0; cc < 128; cc++)
            stage[r * 132 + cc] = valid ? (__uint_as_float(dr[cc]) + sbias[cc]) : 0.0f;
    }
    __syncthreads();
#else
    // Fallback (compute_103 PTX target only; never runs on GB300 — the fatbin's
    // sm_103a cubin wins at load time).
    __syncthreads();
    {
        int r = tid >> 1;
        int c0 = (tid & 1) * 64;
        int gr = row0 + r;
        const unsigned* M = (const unsigned*)mp;
        const float* R = (const float*)rawin;
        const unsigned* W = (const unsigned*)Wq;
        const float* S = (const float*)sc4;
        const float* T = (const float*)sh4;
        for (int j = 0; j < 64; j++) {
            float acc = 0.f;
            if (gr < N_NODES) {
                for (int k = 0; k < 256; k++) {
                    float av;
                    if (k < 128) av = unpackf(M[(size_t)gr * 128 + k]);
                    else {
                        av = R[(size_t)gr * 128 + (k - 128)];
                        if (do_act) av = lkrelu(S[k - 128] * av + T[k - 128]);
                    }
                    acc += av * unpackf(W[(size_t)(c0 + j) * 256 + k]);
                }
            }
            stage[r * 132 + c0 + j] = (gr < N_NODES) ? (acc + sbias[c0 + j]) : 0.0f;
        }
    }
    __syncthreads();
#endif

    // epilogue: column sum/sumsq + coalesced store
    if (tid < 128) {
        float s = 0.f, s2 = 0.f;
#pragma unroll 8
        for (int r = 0; r < 128; r++) {
            float v = stage[r * 132 + tid];
            s += v;
            s2 += v * v;
        }
        atomicAdd(&stats[tid], s);
        atomicAdd(&stats[128 + tid], s2);
    }
#pragma unroll
    for (int it = 0; it < 16; it++) {
        int idx = it * 256 + tid;
        int row = idx >> 5, c4 = idx & 31;
        int gr = row0 + row;
        if (gr < N_NODES) {
            float4 o;
            o.x = stage[row * 132 + c4 * 4 + 0];
            o.y = stage[row * 132 + c4 * 4 + 1];
            o.z = stage[row * 132 + c4 * 4 + 2];
            o.w = stage[row * 132 + c4 * 4 + 3];
            out4[(size_t)gr * 32 + c4] = o;
        }
    }
#if HAS_TC
    __syncthreads();
    if ((tid >> 5) == 0) TC_DEALLOC(tmem, 128);
#endif
}

// ---------------- GraphNorm param compute (also re-zeroes stats) ------------
__global__ void k_zero_stats(float* st) { st[threadIdx.x] = 0.f; }

__global__ void k_stats(float* __restrict__ st, const float* __restrict__ gamma,
                        const float* __restrict__ beta, const float* __restrict__ alpha,
                        float* __restrict__ scale, float* __restrict__ shift) {
    int c = threadIdx.x;
    const float invN = 1.0f / (float)N_NODES;
    float mu = st[c] * invN;
    float a = alpha[c];
    float var = st[c + 128] * invN + mu * mu * (a * a - 2.f * a);
    float r = rsqrtf(var + EPSN);
    float g = gamma[c];
    scale[c] = g * r;
    shift[c] = beta[c] - g * a * mu * r;
    st[c] = 0.f;          // re-zero for next layer
    st[c + 128] = 0.f;
}

// ---------------- final: fused gather + norm + SAGEConv(128->3) + tanh ------
__global__ void k_final(const float4* __restrict__ raw, const int* __restrict__ rowptr,
                        const int* __restrict__ col, const float4* __restrict__ sc4,
                        const float4* __restrict__ sh4, const float* __restrict__ Wlo,
                        const float* __restrict__ Wro, const float* __restrict__ blo,
                        float* __restrict__ out) {
    __shared__ float4 swl[3][32];
    __shared__ float4 swr[3][32];
    __shared__ float sb[3];
    int tid = threadIdx.x;
    if (tid < 96) {
        int o = tid >> 5, l = tid & 31;
        swl[o][l] = ((const float4*)Wlo)[o * 32 + l];
        swr[o][l] = ((const float4*)Wro)[o * 32 + l];
    }
    if (tid < 3) sb[tid] = blo[tid];
    __syncthreads();

    int node = blockIdx.x * 8 + (tid >> 5);
    if (node >= N_NODES) return;
    int lane = tid & 31;
    int beg = __ldg(&rowptr[node]);
    int end = __ldg(&rowptr[node + 1]);
    const float NINF = __int_as_float(0xff800000);
    const float PINF = __int_as_float(0x7f800000);
    float4 mx = make_float4(NINF, NINF, NINF, NINF);
    float4 mn = make_float4(PINF, PINF, PINF, PINF);
    int e = beg;
    for (; e + 3 < end; e += 4) {
        int s0 = __ldg(&col[e]), s1 = __ldg(&col[e + 1]);
        int s2 = __ldg(&col[e + 2]), s3 = __ldg(&col[e + 3]);
        float4 p0 = __ldg(&raw[(size_t)s0 * 32 + lane]);
        float4 p1 = __ldg(&raw[(size_t)s1 * 32 + lane]);
        float4 p2 = __ldg(&raw[(size_t)s2 * 32 + lane]);
        float4 p3 = __ldg(&raw[(size_t)s3 * 32 + lane]);
        mx.x = fmaxf(fmaxf(fmaxf(mx.x, p0.x), fmaxf(p1.x, p2.x)), p3.x);
        mx.y = fmaxf(fmaxf(fmaxf(mx.y, p0.y), fmaxf(p1.y, p2.y)), p3.y);
        mx.z = fmaxf(fmaxf(fmaxf(mx.z, p0.z), fmaxf(p1.z, p2.z)), p3.z);
        mx.w = fmaxf(fmaxf(fmaxf(mx.w, p0.w), fmaxf(p1.w, p2.w)), p3.w);
        mn.x = fminf(fminf(fminf(mn.x, p0.x), fminf(p1.x, p2.x)), p3.x);
        mn.y = fminf(fminf(fminf(mn.y, p0.y), fminf(p1.y, p2.y)), p3.y);
        mn.z = fminf(fminf(fminf(mn.z, p0.z), fminf(p1.z, p2.z)), p3.z);
        mn.w = fminf(fminf(fminf(mn.w, p0.w), fminf(p1.w, p2.w)), p3.w);
    }
    for (; e < end; e++) {
        int s = __ldg(&col[e]);
        float4 p = __ldg(&raw[(size_t)s * 32 + lane]);
        mx.x = fmaxf(mx.x, p.x); mx.y = fmaxf(mx.y, p.y);
        mx.z = fmaxf(mx.z, p.z); mx.w = fmaxf(mx.w, p.w);
        mn.x = fminf(mn.x, p.x); mn.y = fminf(mn.y, p.y);
        mn.z = fminf(mn.z, p.z); mn.w = fminf(mn.w, p.w);
    }
    float4 s = __ldg(&sc4[lane]);
    float4 t = __ldg(&sh4[lane]);
    float mv[4];
    if (beg == end) {
        mv[0] = mv[1] = mv[2] = mv[3] = 0.f;
    } else {
        mv[0] = lkrelu(fmaf(s.x, (s.x >= 0.f) ? mx.x : mn.x, t.x));
        mv[1] = lkrelu(fmaf(s.y, (s.y >= 0.f) ? mx.y : mn.y, t.y));
        mv[2] = lkrelu(fmaf(s.z, (s.z >= 0.f) ? mx.z : mn.z, t.z));
        mv[3] = lkrelu(fmaf(s.w, (s.w >= 0.f) ? mx.w : mn.w, t.w));
    }
    float4 hr = __ldg(&raw[(size_t)node * 32 + lane]);
    float hv[4];
    hv[0] = lkrelu(fmaf(s.x, hr.x, t.x));
    hv[1] = lkrelu(fmaf(s.y, hr.y, t.y));
    hv[2] = lkrelu(fmaf(s.z, hr.z, t.z));
    hv[3] = lkrelu(fmaf(s.w, hr.w, t.w));

    float p[3];
#pragma unroll
    for (int o = 0; o < 3; o++) {
        float4 wl = swl[o][lane];
        float4 wr = swr[o][lane];
        p[o] = mv[0] * wl.x + mv[1] * wl.y + mv[2] * wl.z + mv[3] * wl.w +
               hv[0] * wr.x + hv[1] * wr.y + hv[2] * wr.z + hv[3] * wr.w;
    }
#pragma unroll
    for (int d = 16; d; d >>= 1) {
#pragma unroll
        for (int o = 0; o < 3; o++) p[o] += __shfl_down_sync(0xffffffffu, p[o], d);
    }
    if (lane == 0) {
#pragma unroll
        for (int o = 0; o < 3; o++)
            out[(size_t)node * 3 + o] = tanhf(p[o] + sb[o]) * 0.5f;
    }
}

// ---------------- host launcher ----------------
extern "C" void kernel_launch(void* const* d_in, const int* in_sizes, int n_in,
                              void* d_out, int out_size) {
    const float* x     = (const float*)d_in[0];
    const int*   ei    = (const int*)d_in[1];
    const float* Wl    = (const float*)d_in[2];
    const float* bl    = (const float*)d_in[3];
    const float* Wr    = (const float*)d_in[4];
    const float* Wlo   = (const float*)d_in[5];
    const float* blo   = (const float*)d_in[6];
    const float* Wro   = (const float*)d_in[7];
    const float* gamma = (const float*)d_in[8];
    const float* beta  = (const float*)d_in[9];
    const float* alpha = (const float*)d_in[10];

    float4* raw;
    uint4* mp;
    unsigned* wp;
    float *stats, *scale, *shift;
    int *deg, *rowptr, *cursor, *col;
    cudaGetSymbolAddress((void**)&raw, g_raw);
    cudaGetSymbolAddress((void**)&mp, g_mp);
    cudaGetSymbolAddress((void**)&wp, g_wp);
    cudaGetSymbolAddress((void**)&stats, g_stats);
    cudaGetSymbolAddress((void**)&scale, g_scale);
    cudaGetSymbolAddress((void**)&shift, g_shift);
    cudaGetSymbolAddress((void**)&deg, g_deg);
    cudaGetSymbolAddress((void**)&rowptr, g_rowptr);
    cudaGetSymbolAddress((void**)&cursor, g_cursor);
    cudaGetSymbolAddress((void**)&col, g_col);

    cudaFuncSetAttribute(k_gemm, cudaFuncAttributeMaxDynamicSharedMemorySize, GEMM_DYN);

    const int* src = ei;
    const int* dst = ei + N_EDGES;

    // CSR build
    k_zero_deg<<<(N_NODES + 255) / 256, 256>>>(deg);
    k_count<<<(N_EDGES + 255) / 256, 256>>>(dst, deg);
    k_scan<<<1, 1024>>>(deg, rowptr, cursor);
    k_fill<<<(N_EDGES + 255) / 256, 256>>>(src, dst, cursor, col);

    // weight packing (once)
    k_wconv<<<(6 * 128 * 256 + 255) / 256, 256>>>(Wl, Wr, wp);
    k_zero_stats<<<1, 256>>>(stats);

    const int gemm_grid = (N_NODES + 127) / 128;
    const float4* sc4 = (const float4*)scale;
    const float4* sh4 = (const float4*)shift;
    for (int L = 0; L < 6; L++) {
        const float4* rawin = (L == 0) ? (const float4*)x : (const float4*)raw;
        int do_act = (L > 0) ? 1 : 0;
        k_gather<<<(N_NODES + 7) / 8, 256>>>(rawin, rowptr, col, mp, sc4, sh4, do_act);
        k_gemm<<<gemm_grid, 256, GEMM_DYN>>>(mp, rawin, (const uint4*)(wp + L * 32768),
                                             sc4, sh4, do_act, bl + L * NF, raw, stats);
        k_stats<<<1, 128>>>(stats, gamma + L * NF, beta + L * NF, alpha + L * NF,
                            scale, shift);
    }
    k_final<<<(N_NODES + 7) / 8, 256>>>((const float4*)raw, rowptr, col, sc4, sh4,
                                        Wlo, Wro, blo, (float*)d_out);
}